// round 14
// baseline (speedup 1.0000x reference)
#include <cuda_runtime.h>
#include <math.h>
#include <stdint.h>

#define BB 2
#define SS 2048
#define EE 512
#define NHH 8
#define BH (BB*NHH)
#define NCHUNK (SS/64)

typedef unsigned long long ull;

// Scratch (device globals: allocation-free)
__device__ float g_ig[BH*SS];
__device__ float g_fg[BH*SS];
__device__ float g_u [BH*SS];      // ig_j - cs_j
__device__ float g_M [BH*SS];      // prefix max of u
__device__ float g_m [BH*SS];      // cs_i + M_i
__device__ float g_w [BH*SS];      // exp(u_j - cmax_of_chunk)
__device__ float g_cmax[BH*NCHUNK];

__device__ __forceinline__ ull fma2(ull a, ull b, ull c) {
    ull d;
    asm("fma.rn.f32x2 %0, %1, %2, %3;" : "=l"(d) : "l"(a), "l"(b), "l"(c));
    return d;
}
__device__ __forceinline__ float2 unpack2(ull v) {
    float2 r;
    asm("mov.b64 {%0, %1}, %2;" : "=f"(r.x), "=f"(r.y) : "l"(v));
    return r;
}
__device__ __forceinline__ uint32_t s2u(const void* p) {
    uint32_t a;
    asm("{ .reg .u64 t; cvta.to.shared.u64 t, %1; cvt.u32.u64 %0, t; }"
        : "=r"(a) : "l"(p));
    return a;
}
__device__ __forceinline__ void cp16(uint32_t d, const void* s) {
    asm volatile("cp.async.cg.shared.global [%0], [%1], 16;" :: "r"(d), "l"(s));
}
#define CP_COMMIT() asm volatile("cp.async.commit_group;")
template<int N> __device__ __forceinline__ void cp_wait() {
    asm volatile("cp.async.wait_group %0;" :: "n"(N));
}

// m16n8k8 tf32 mma (row-major A, col-major B), accumulate in place
__device__ __forceinline__ void mma_tf32(float& d0, float& d1, float& d2, float& d3,
                                         uint32_t a0, uint32_t a1, uint32_t a2, uint32_t a3,
                                         uint32_t b0, uint32_t b1) {
    asm volatile(
        "mma.sync.aligned.m16n8k8.row.col.f32.tf32.tf32.f32 "
        "{%0,%1,%2,%3}, {%4,%5,%6,%7}, {%8,%9}, {%0,%1,%2,%3};"
        : "+f"(d0), "+f"(d1), "+f"(d2), "+f"(d3)
        : "r"(a0), "r"(a1), "r"(a2), "r"(a3), "r"(b0), "r"(b1));
}

// ---------------------------------------------------------------------------
// Kernel 1: gate projections, float4 + f32x2 inner loop.
// Lane owns columns t4*128 + lane*4 .. +3. Per k-chunk: 1 LDG.128 (W, L1
// broadcast) + 8 LDS.128 + 16 fma2.  ~2.7x fewer issues than R12.
// grid = B*S/8 blocks, 512 threads (warp w -> head (w&7), gate (w>>3))
// ---------------------------------------------------------------------------
__global__ void __launch_bounds__(512)
gates_kernel(const float* __restrict__ q,
             const float* __restrict__ k,
             const float* __restrict__ v,
             const float* __restrict__ Wi,
             const float* __restrict__ bi,
             const float* __restrict__ Wf,
             const float* __restrict__ bf) {
    __shared__ float gin[8 * 1536];   // 48 KB
    const int tid = threadIdx.x;
    const int r0  = blockIdx.x * 8;

    const float4* q4 = (const float4*)q;
    const float4* k4 = (const float4*)k;
    const float4* v4 = (const float4*)v;
    float4* gin4 = (float4*)gin;
    for (int idx = tid; idx < 8 * 384; idx += 512) {
        int row = idx / 384;
        int c4  = idx - row * 384;
        int r   = r0 + row;
        float4 val;
        if (c4 < 128)       val = q4[r * 128 + c4];
        else if (c4 < 256)  val = k4[r * 128 + (c4 - 128)];
        else                val = v4[r * 128 + (c4 - 256)];
        gin4[row * 384 + c4] = val;
    }
    __syncthreads();

    const int wid  = tid >> 5;
    const int lane = tid & 31;
    const int n    = wid & 7;
    const int isF  = wid >> 3;
    const float* Wbase = (isF ? Wf : Wi) + n * 1536 + lane * 4;
    const float* g0    = gin + lane * 4;
    const float bias = isF ? bf[n] : bi[n];

    ull acc2[8];
    #pragma unroll
    for (int r = 0; r < 8; r++) acc2[r] = 0ull;

    #pragma unroll
    for (int t4 = 0; t4 < 12; t4++) {
        ulonglong2 wv = *(const ulonglong2*)(Wbase + t4 * 128);
        #pragma unroll
        for (int r = 0; r < 8; r++) {
            ulonglong2 gv = *(const ulonglong2*)(g0 + r * 1536 + t4 * 128);
            acc2[r] = fma2(gv.x, wv.x, acc2[r]);
            acc2[r] = fma2(gv.y, wv.y, acc2[r]);
        }
    }

    float* dst = isF ? g_fg : g_ig;
    #pragma unroll
    for (int r = 0; r < 8; r++) {
        float2 pr = unpack2(acc2[r]);
        float a = pr.x + pr.y;
        #pragma unroll
        for (int o = 16; o > 0; o >>= 1) a += __shfl_xor_sync(0xffffffffu, a, o);
        if (lane == 0) {
            int rr = r0 + r;
            int b = rr / SS, sIdx = rr - b * SS;
            dst[(b * NHH + n) * SS + sIdx] = a + bias;
        }
    }
}

// ---------------------------------------------------------------------------
// Kernel 2: per-(b,n) scan (unchanged).
// ---------------------------------------------------------------------------
__global__ void scan_kernel() {
    __shared__ float sh[256];
    const int bh   = blockIdx.x;
    const int tid  = threadIdx.x;
    const int base = bh * SS + tid * 8;

    float csl[8];
    float run = 0.f;
    #pragma unroll
    for (int t = 0; t < 8; t++) {
        float x  = g_fg[base + t];
        float ls = fminf(x, 0.f) - log1pf(expf(-fabsf(x)));
        run += ls;
        csl[t] = run;
    }
    sh[tid] = run;
    __syncthreads();
    #pragma unroll
    for (int off = 1; off < 256; off <<= 1) {
        float vv = (tid >= off) ? sh[tid - off] : 0.f;
        __syncthreads();
        sh[tid] += vv;
        __syncthreads();
    }
    float offs = (tid > 0) ? sh[tid - 1] : 0.f;

    float u[8], pm[8];
    float runm = -INFINITY;
    #pragma unroll
    for (int t = 0; t < 8; t++) {
        float cs = offs + csl[t];
        csl[t] = cs;
        float ut = g_ig[base + t] - cs;
        u[t] = ut;
        runm = fmaxf(runm, ut);
        pm[t] = runm;
    }
    float cm = runm;
    cm = fmaxf(cm, __shfl_xor_sync(0xffffffffu, cm, 1));
    cm = fmaxf(cm, __shfl_xor_sync(0xffffffffu, cm, 2));
    cm = fmaxf(cm, __shfl_xor_sync(0xffffffffu, cm, 4));
    if ((tid & 7) == 0) g_cmax[bh * NCHUNK + (tid >> 3)] = cm;

    __syncthreads();
    sh[tid] = runm;
    __syncthreads();
    #pragma unroll
    for (int off = 1; off < 256; off <<= 1) {
        float vv = (tid >= off) ? sh[tid - off] : -INFINITY;
        __syncthreads();
        sh[tid] = fmaxf(sh[tid], vv);
        __syncthreads();
    }
    float moffs = (tid > 0) ? sh[tid - 1] : -INFINITY;
    #pragma unroll
    for (int t = 0; t < 8; t++) {
        float Mi = fmaxf(moffs, pm[t]);
        g_u[base + t] = u[t];
        g_M[base + t] = Mi;
        g_m[base + t] = csl[t] + Mi;
        g_w[base + t] = __expf(u[t] - cm);
    }
}

// ---------------------------------------------------------------------------
// Kernel 3: tf32 mma.sync attention, 2 syncs per chunk (prefetch moved to
// loop top; SYNC_B proves buffer p^1 free). Fragments identical to R12.
// ---------------------------------------------------------------------------
// smem float offsets
#define QS_OFF 0          // Qs[64][68]
#define KS_OFF 4352       // Ks[2][64][68]
#define VS_OFF 13056      // Vs[2][64][72]
#define PS_OFF 22272      // Ps[64][68] (also O staging in epilogue)
#define WB_OFF 26624      // Wb[2][64]
#define UB_OFF 26752      // Ub[2][64]
#define MS_OFF 26880      // Ms[64]
#define CS_OFF 26944      // Cs[32]
#define ATTN_SMEM_FLOATS 26976
#define ATTN_SMEM_BYTES (ATTN_SMEM_FLOATS * 4)

__global__ void __launch_bounds__(256, 2)
attn_kernel(const float* __restrict__ q,
            const float* __restrict__ k,
            const float* __restrict__ v,
            float* __restrict__ out) {
    extern __shared__ float sm[];
    __shared__ int s_cstart;

    const int bh  = blockIdx.y;
    const int b   = bh >> 3;
    const int n   = bh & 7;
    const int ti  = (int)gridDim.x - 1 - (int)blockIdx.x;   // big tiles first
    const int tid = threadIdx.x;
    const int lane = tid & 31;
    const int wi  = (tid >> 5) & 3;      // i-block (16 rows)
    const int wj  = tid >> 7;            // j/d half (32 cols)
    const int g8  = lane >> 2;           // fragment group 0..7
    const int tg  = lane & 3;            // thread-in-group 0..3
    const int i0w = wi * 16;

    const int i0 = ti * 64;
    const float* qg  = q + (size_t)(b * SS + i0) * EE + n * 64;
    const float* kg0 = k + (size_t)(b * SS) * EE + n * 64;
    const float* vg0 = v + (size_t)(b * SS) * EE + n * 64;

    const uint32_t qs_a = s2u(sm + QS_OFF);
    const uint32_t ks_a = s2u(sm + KS_OFF);
    const uint32_t vs_a = s2u(sm + VS_OFF);
    const uint32_t wb_a = s2u(sm + WB_OFF);
    const uint32_t ub_a = s2u(sm + UB_OFF);
    const uint32_t ms_a = s2u(sm + MS_OFF);

    // warp 0: cmax cache + truncation-start ballot
    if (tid < 32) {
        float thr = g_M[bh * SS + i0] - 88.0f;
        float cmv = g_cmax[bh * NCHUNK + tid];
        sm[CS_OFF + tid] = cmv;
        bool live = (cmv > thr) && (tid < ti);
        unsigned msk = __ballot_sync(0xffffffffu, live);
        if (tid == 0) s_cstart = msk ? (__ffs(msk) - 1) : ti;
    }

    // group A: Q + Ms
    #pragma unroll
    for (int t = 0; t < 4; t++) {
        int s = tid + 256 * t, row = s >> 4, c16 = s & 15;
        cp16(qs_a + (uint32_t)(row * 272 + c16 * 16), qg + row * EE + c16 * 4);
    }
    if (tid < 16) cp16(ms_a + tid * 16u, g_M + bh * SS + i0 + tid * 4);
    CP_COMMIT();
    cp_wait<0>();
    __syncthreads();

    const int c_start = s_cstart;
    const float M0 = sm[MS_OFF + i0w + g8];
    const float M1 = sm[MS_OFF + i0w + g8 + 8];

#define STAGE_CH(cc, bufidx) do {                                             \
    int j0_ = (cc) * 64;                                                      \
    _Pragma("unroll")                                                         \
    for (int t_ = 0; t_ < 4; t_++) {                                          \
        int s_ = tid + 256 * t_, row_ = s_ >> 4, c16_ = s_ & 15;              \
        cp16(ks_a + (uint32_t)((bufidx) * 17408 + row_ * 272 + c16_ * 16),    \
             kg0 + (size_t)(j0_ + row_) * EE + c16_ * 4);                     \
        cp16(vs_a + (uint32_t)((bufidx) * 18432 + row_ * 288 + c16_ * 16),    \
             vg0 + (size_t)(j0_ + row_) * EE + c16_ * 4);                     \
    }                                                                         \
    if (tid < 16)                                                             \
        cp16(wb_a + (bufidx) * 256u + tid * 16u, g_w + bh * SS + j0_ + tid * 4); \
    else if (tid < 32)                                                        \
        cp16(ub_a + (bufidx) * 256u + (tid - 16) * 16u,                       \
             g_u + bh * SS + j0_ + (tid - 16) * 4);                           \
} while (0)

    STAGE_CH(c_start, 0);
    CP_COMMIT();
    cp_wait<0>();
    __syncthreads();                     // chunk c_start visible

    float o[4][4];
    #pragma unroll
    for (int t = 0; t < 4; t++)
        #pragma unroll
        for (int r = 0; r < 4; r++) o[t][r] = 0.f;
    float ssum_part = 0.f;

    for (int c = c_start; c <= ti; c++) {
        const int p = (c - c_start) & 1;

        // prefetch chunk c+1 into buffer p^1 (safe: SYNC_B of iter c-1
        // guarantees all warps finished reading buffer p^1)
        if (c < ti) {
            STAGE_CH(c + 1, p ^ 1);
            CP_COMMIT();
        }

        const float* Ksp = sm + KS_OFF + p * 4352;
        const float* Vsp = sm + VS_OFF + p * 4608;

        // ---- GEMM1: S = Q.K^T (tf32 mma) ----
        float s4[4][4];
        #pragma unroll
        for (int t = 0; t < 4; t++)
            #pragma unroll
            for (int r = 0; r < 4; r++) s4[t][r] = 0.f;
        #pragma unroll
        for (int ks = 0; ks < 8; ks++) {
            const int k0 = ks * 8;
            const float* qb = sm + QS_OFF + (i0w + g8) * 68 + k0 + tg;
            uint32_t a0 = __float_as_uint(qb[0]);
            uint32_t a1 = __float_as_uint(qb[8 * 68]);
            uint32_t a2 = __float_as_uint(qb[4]);
            uint32_t a3 = __float_as_uint(qb[8 * 68 + 4]);
            #pragma unroll
            for (int t = 0; t < 4; t++) {
                const int j0 = wj * 32 + t * 8;
                const float* kbp = Ksp + (j0 + g8) * 68 + k0 + tg;
                uint32_t b0 = __float_as_uint(kbp[0]);
                uint32_t b1 = __float_as_uint(kbp[4]);
                mma_tf32(s4[t][0], s4[t][1], s4[t][2], s4[t][3],
                         a0, a1, a2, a3, b0, b1);
            }
        }

        // ---- P = scale(S), store to Ps ----
        if (c < ti) {
            const float csc = sm[CS_OFF + c];
            const float e0 = 0.125f * __expf(csc - M0);
            const float e1 = 0.125f * __expf(csc - M1);
            #pragma unroll
            for (int t = 0; t < 4; t++) {
                const int jc = wj * 32 + t * 8 + tg * 2;
                float2 wv = *(const float2*)(sm + WB_OFF + p * 64 + jc);
                float2 hi = make_float2(s4[t][0] * e0 * wv.x, s4[t][1] * e0 * wv.y);
                float2 lo = make_float2(s4[t][2] * e1 * wv.x, s4[t][3] * e1 * wv.y);
                *(float2*)(sm + PS_OFF + (i0w + g8) * 68 + jc)     = hi;
                *(float2*)(sm + PS_OFF + (i0w + g8 + 8) * 68 + jc) = lo;
            }
        } else {
            const int il0 = i0w + g8, il1 = il0 + 8;
            #pragma unroll
            for (int t = 0; t < 4; t++) {
                const int jc = wj * 32 + t * 8 + tg * 2;
                float2 uv = *(const float2*)(sm + UB_OFF + p * 64 + jc);
                float p0 = (jc     <= il0) ? s4[t][0] * 0.125f * __expf(uv.x - M0) : 0.f;
                float p1 = (jc + 1 <= il0) ? s4[t][1] * 0.125f * __expf(uv.y - M0) : 0.f;
                float p2 = (jc     <= il1) ? s4[t][2] * 0.125f * __expf(uv.x - M1) : 0.f;
                float p3 = (jc + 1 <= il1) ? s4[t][3] * 0.125f * __expf(uv.y - M1) : 0.f;
                *(float2*)(sm + PS_OFF + (i0w + g8) * 68 + jc)     = make_float2(p0, p1);
                *(float2*)(sm + PS_OFF + (i0w + g8 + 8) * 68 + jc) = make_float2(p2, p3);
            }
        }
        __syncthreads();                 // SYNC_A: Ps visible

        // ---- ssum partial (row = tid>>2, quarter = tid&3) ----
        {
            const int srow = tid >> 2, sq = tid & 3;
            const float4* pr = (const float4*)(sm + PS_OFF + srow * 68 + sq * 16);
            float4 x0 = pr[0], x1 = pr[1], x2 = pr[2], x3 = pr[3];
            ssum_part += (((x0.x + x0.y) + (x0.z + x0.w))
                        + ((x1.x + x1.y) + (x1.z + x1.w)))
                       + (((x2.x + x2.y) + (x2.z + x2.w))
                        + ((x3.x + x3.y) + (x3.z + x3.w)));
        }

        // ---- GEMM2: O += P.V (tf32 mma) ----
        #pragma unroll
        for (int ks = 0; ks < 8; ks++) {
            const int k0j = ks * 8;
            const float* pb = sm + PS_OFF + (i0w + g8) * 68 + k0j + tg;
            uint32_t a0 = __float_as_uint(pb[0]);
            uint32_t a1 = __float_as_uint(pb[8 * 68]);
            uint32_t a2 = __float_as_uint(pb[4]);
            uint32_t a3 = __float_as_uint(pb[8 * 68 + 4]);
            #pragma unroll
            for (int t = 0; t < 4; t++) {
                const int d0c = wj * 32 + t * 8;
                const float* vbp = Vsp + (k0j + tg) * 72 + d0c + g8;
                uint32_t b0 = __float_as_uint(vbp[0]);
                uint32_t b1 = __float_as_uint(vbp[4 * 72]);
                mma_tf32(o[t][0], o[t][1], o[t][2], o[t][3],
                         a0, a1, a2, a3, b0, b1);
            }
        }

        if (c < ti) cp_wait<0>();        // chunk c+1 landed
        __syncthreads();                 // SYNC_B: next iter may reuse buffers
    }
#undef STAGE_CH

    // ---- epilogue (last SYNC_B fences GEMM2 reads of Ps) ----
    #pragma unroll
    for (int t = 0; t < 4; t++) {
        const int dc = wj * 32 + t * 8 + tg * 2;
        *(float2*)(sm + PS_OFF + (i0w + g8) * 68 + dc)     = make_float2(o[t][0], o[t][1]);
        *(float2*)(sm + PS_OFF + (i0w + g8 + 8) * 68 + dc) = make_float2(o[t][2], o[t][3]);
    }
    __syncthreads();

    {
        const int row = tid >> 2, qq = tid & 3;
        float ss = ssum_part;
        ss += __shfl_xor_sync(0xffffffffu, ss, 1);
        ss += __shfl_xor_sync(0xffffffffu, ss, 2);

        const int gi = bh * SS + i0 + row;
        const float mi   = g_m[gi];
        const float norm = fmaxf(fabsf(ss), __expf(-mi)) + 1e-6f;
        const float inv  = 1.0f / norm;

        const float4* orp = (const float4*)(sm + PS_OFF + row * 68 + qq * 16);
        float4 y0 = orp[0], y1 = orp[1], y2 = orp[2], y3 = orp[3];

        float sum = (((y0.x + y0.y) + (y0.z + y0.w))
                   + ((y1.x + y1.y) + (y1.z + y1.w)))
                  + (((y2.x + y2.y) + (y2.z + y2.w))
                   + ((y3.x + y3.y) + (y3.z + y3.w)));
        sum += __shfl_xor_sync(0xffffffffu, sum, 1);
        sum += __shfl_xor_sync(0xffffffffu, sum, 2);
        const float mu = sum * inv * (1.0f / 64.0f);

        float vals[16] = {y0.x, y0.y, y0.z, y0.w, y1.x, y1.y, y1.z, y1.w,
                          y2.x, y2.y, y2.z, y2.w, y3.x, y3.y, y3.z, y3.w};
        float var = 0.f;
        #pragma unroll
        for (int e = 0; e < 16; e++) {
            float dx = vals[e] * inv - mu;
            var += dx * dx;
        }
        var += __shfl_xor_sync(0xffffffffu, var, 1);
        var += __shfl_xor_sync(0xffffffffu, var, 2);
        const float sc = rsqrtf(var * (1.0f / 64.0f) + 1e-5f);

        float* op = out + (size_t)gi * 64 + qq * 16;
        #pragma unroll
        for (int e4 = 0; e4 < 4; e4++) {
            *(float4*)(op + e4 * 4) = make_float4(
                (vals[e4 * 4 + 0] * inv - mu) * sc,
                (vals[e4 * 4 + 1] * inv - mu) * sc,
                (vals[e4 * 4 + 2] * inv - mu) * sc,
                (vals[e4 * 4 + 3] * inv - mu) * sc);
        }
    }
}

// ---------------------------------------------------------------------------
extern "C" void kernel_launch(void* const* d_in, const int* in_sizes, int n_in,
                              void* d_out, int out_size) {
    const float* q  = (const float*)d_in[0];
    const float* k  = (const float*)d_in[1];
    const float* v  = (const float*)d_in[2];
    const float* Wi = (const float*)d_in[3];
    const float* bi = (const float*)d_in[4];
    const float* Wf = (const float*)d_in[5];
    const float* bf = (const float*)d_in[6];
    float* out = (float*)d_out;

    cudaFuncSetAttribute(attn_kernel,
                         cudaFuncAttributeMaxDynamicSharedMemorySize,
                         ATTN_SMEM_BYTES);

    gates_kernel<<<(BB * SS) / 8, 512>>>(q, k, v, Wi, bi, Wf, bf);
    scan_kernel<<<BH, 256>>>();
    attn_kernel<<<dim3(SS / 64, BH), 256, ATTN_SMEM_BYTES>>>(q, k, v, out);
}

// round 15
// speedup vs baseline: 1.0579x; 1.0579x over previous
#include <cuda_runtime.h>
#include <math.h>
#include <stdint.h>

#define BB 2
#define SS 2048
#define EE 512
#define NHH 8
#define BH (BB*NHH)
#define NCHUNK (SS/64)

typedef unsigned long long ull;

// Scratch (device globals: allocation-free)
__device__ float g_ig[BH*SS];
__device__ float g_fg[BH*SS];
__device__ float g_u [BH*SS];      // ig_j - cs_j
__device__ float g_M [BH*SS];      // prefix max of u
__device__ float g_m [BH*SS];      // cs_i + M_i
__device__ float g_w [BH*SS];      // exp(u_j - cmax_of_chunk)
__device__ float g_cmax[BH*NCHUNK];

__device__ __forceinline__ uint32_t s2u(const void* p) {
    uint32_t a;
    asm("{ .reg .u64 t; cvta.to.shared.u64 t, %1; cvt.u32.u64 %0, t; }"
        : "=r"(a) : "l"(p));
    return a;
}
__device__ __forceinline__ void cp16(uint32_t d, const void* s) {
    asm volatile("cp.async.cg.shared.global [%0], [%1], 16;" :: "r"(d), "l"(s));
}
#define CP_COMMIT() asm volatile("cp.async.commit_group;")
template<int N> __device__ __forceinline__ void cp_wait() {
    asm volatile("cp.async.wait_group %0;" :: "n"(N));
}

// m16n8k8 tf32 mma (row-major A, col-major B), accumulate in place
__device__ __forceinline__ void mma_tf32(float& d0, float& d1, float& d2, float& d3,
                                         uint32_t a0, uint32_t a1, uint32_t a2, uint32_t a3,
                                         uint32_t b0, uint32_t b1) {
    asm volatile(
        "mma.sync.aligned.m16n8k8.row.col.f32.tf32.tf32.f32 "
        "{%0,%1,%2,%3}, {%4,%5,%6,%7}, {%8,%9}, {%0,%1,%2,%3};"
        : "+f"(d0), "+f"(d1), "+f"(d2), "+f"(d3)
        : "r"(a0), "r"(a1), "r"(a2), "r"(a3), "r"(b0), "r"(b1));
}

// ---------------------------------------------------------------------------
// Kernel 1: gate projections — R12 proven version (31 regs, occ 70%, 26.6us).
// ---------------------------------------------------------------------------
__global__ void __launch_bounds__(512)
gates_kernel(const float* __restrict__ q,
             const float* __restrict__ k,
             const float* __restrict__ v,
             const float* __restrict__ Wi,
             const float* __restrict__ bi,
             const float* __restrict__ Wf,
             const float* __restrict__ bf) {
    __shared__ float gin[8 * 1536];   // 48 KB
    const int tid = threadIdx.x;
    const int r0  = blockIdx.x * 8;

    const float4* q4 = (const float4*)q;
    const float4* k4 = (const float4*)k;
    const float4* v4 = (const float4*)v;
    float4* gin4 = (float4*)gin;
    for (int idx = tid; idx < 8 * 384; idx += 512) {
        int row = idx / 384;
        int c4  = idx - row * 384;
        int r   = r0 + row;
        float4 val;
        if (c4 < 128)       val = q4[r * 128 + c4];
        else if (c4 < 256)  val = k4[r * 128 + (c4 - 128)];
        else                val = v4[r * 128 + (c4 - 256)];
        gin4[row * 384 + c4] = val;
    }
    __syncthreads();

    const int wid  = tid >> 5;
    const int lane = tid & 31;
    const int n    = wid & 7;
    const int isF  = wid >> 3;
    const float* W  = (isF ? Wf : Wi) + n * 1536 + lane;
    const float* g0 = gin + lane;
    const float bias = isF ? bf[n] : bi[n];

    float acc[8] = {0.f, 0.f, 0.f, 0.f, 0.f, 0.f, 0.f, 0.f};
    for (int t = 0; t < 48; t++) {
        float wv = W[t * 32];
        const float* gp = g0 + t * 32;
        #pragma unroll
        for (int r = 0; r < 8; r++) acc[r] += gp[r * 1536] * wv;
    }

    float* dst = isF ? g_fg : g_ig;
    #pragma unroll
    for (int r = 0; r < 8; r++) {
        float a = acc[r];
        #pragma unroll
        for (int o = 16; o > 0; o >>= 1) a += __shfl_xor_sync(0xffffffffu, a, o);
        if (lane == 0) {
            int rr = r0 + r;
            int b = rr / SS, sIdx = rr - b * SS;
            dst[(b * NHH + n) * SS + sIdx] = a + bias;
        }
    }
}

// ---------------------------------------------------------------------------
// Kernel 2: per-(b,n) scan (unchanged).
// ---------------------------------------------------------------------------
__global__ void scan_kernel() {
    __shared__ float sh[256];
    const int bh   = blockIdx.x;
    const int tid  = threadIdx.x;
    const int base = bh * SS + tid * 8;

    float csl[8];
    float run = 0.f;
    #pragma unroll
    for (int t = 0; t < 8; t++) {
        float x  = g_fg[base + t];
        float ls = fminf(x, 0.f) - log1pf(expf(-fabsf(x)));
        run += ls;
        csl[t] = run;
    }
    sh[tid] = run;
    __syncthreads();
    #pragma unroll
    for (int off = 1; off < 256; off <<= 1) {
        float vv = (tid >= off) ? sh[tid - off] : 0.f;
        __syncthreads();
        sh[tid] += vv;
        __syncthreads();
    }
    float offs = (tid > 0) ? sh[tid - 1] : 0.f;

    float u[8], pm[8];
    float runm = -INFINITY;
    #pragma unroll
    for (int t = 0; t < 8; t++) {
        float cs = offs + csl[t];
        csl[t] = cs;
        float ut = g_ig[base + t] - cs;
        u[t] = ut;
        runm = fmaxf(runm, ut);
        pm[t] = runm;
    }
    float cm = runm;
    cm = fmaxf(cm, __shfl_xor_sync(0xffffffffu, cm, 1));
    cm = fmaxf(cm, __shfl_xor_sync(0xffffffffu, cm, 2));
    cm = fmaxf(cm, __shfl_xor_sync(0xffffffffu, cm, 4));
    if ((tid & 7) == 0) g_cmax[bh * NCHUNK + (tid >> 3)] = cm;

    __syncthreads();
    sh[tid] = runm;
    __syncthreads();
    #pragma unroll
    for (int off = 1; off < 256; off <<= 1) {
        float vv = (tid >= off) ? sh[tid - off] : -INFINITY;
        __syncthreads();
        sh[tid] = fmaxf(sh[tid], vv);
        __syncthreads();
    }
    float moffs = (tid > 0) ? sh[tid - 1] : -INFINITY;
    #pragma unroll
    for (int t = 0; t < 8; t++) {
        float Mi = fmaxf(moffs, pm[t]);
        g_u[base + t] = u[t];
        g_M[base + t] = Mi;
        g_m[base + t] = csl[t] + Mi;
        g_w[base + t] = __expf(u[t] - cm);
    }
}

// ---------------------------------------------------------------------------
// Kernel 3: tf32 mma.sync attention. vs R12/R14: Q fragments hoisted to
// registers (A-side LDS removed from the loop), ssum accumulated in
// registers across chunks (per-chunk Ps re-read removed), 2 syncs/chunk.
// ---------------------------------------------------------------------------
// smem float offsets
#define QS_OFF 0          // Qs[64][68]
#define KS_OFF 4352       // Ks[2][64][68]
#define VS_OFF 13056      // Vs[2][64][72]
#define PS_OFF 22272      // Ps[64][68] (also O staging in epilogue)
#define WB_OFF 26624      // Wb[2][64]
#define UB_OFF 26752      // Ub[2][64]
#define MS_OFF 26880      // Ms[64]
#define CS_OFF 26944      // Cs[32]
#define SSUM_OFF 26976    // ssum partials [2][64]
#define ATTN_SMEM_FLOATS 27104
#define ATTN_SMEM_BYTES (ATTN_SMEM_FLOATS * 4)

__global__ void __launch_bounds__(256, 2)
attn_kernel(const float* __restrict__ q,
            const float* __restrict__ k,
            const float* __restrict__ v,
            float* __restrict__ out) {
    extern __shared__ float sm[];
    __shared__ int s_cstart;

    const int bh  = blockIdx.y;
    const int b   = bh >> 3;
    const int n   = bh & 7;
    const int ti  = (int)gridDim.x - 1 - (int)blockIdx.x;   // big tiles first
    const int tid = threadIdx.x;
    const int lane = tid & 31;
    const int wi  = (tid >> 5) & 3;      // i-block (16 rows)
    const int wj  = tid >> 7;            // j/d half (32 cols)
    const int g8  = lane >> 2;           // fragment group 0..7
    const int tg  = lane & 3;            // thread-in-group 0..3
    const int i0w = wi * 16;

    const int i0 = ti * 64;
    const float* qg  = q + (size_t)(b * SS + i0) * EE + n * 64;
    const float* kg0 = k + (size_t)(b * SS) * EE + n * 64;
    const float* vg0 = v + (size_t)(b * SS) * EE + n * 64;

    const uint32_t qs_a = s2u(sm + QS_OFF);
    const uint32_t ks_a = s2u(sm + KS_OFF);
    const uint32_t vs_a = s2u(sm + VS_OFF);
    const uint32_t wb_a = s2u(sm + WB_OFF);
    const uint32_t ub_a = s2u(sm + UB_OFF);
    const uint32_t ms_a = s2u(sm + MS_OFF);

    // warp 0: cmax cache + truncation-start ballot
    if (tid < 32) {
        float thr = g_M[bh * SS + i0] - 88.0f;
        float cmv = g_cmax[bh * NCHUNK + tid];
        sm[CS_OFF + tid] = cmv;
        bool live = (cmv > thr) && (tid < ti);
        unsigned msk = __ballot_sync(0xffffffffu, live);
        if (tid == 0) s_cstart = msk ? (__ffs(msk) - 1) : ti;
    }

    // group A: Q + Ms
    #pragma unroll
    for (int t = 0; t < 4; t++) {
        int s = tid + 256 * t, row = s >> 4, c16 = s & 15;
        cp16(qs_a + (uint32_t)(row * 272 + c16 * 16), qg + row * EE + c16 * 4);
    }
    if (tid < 16) cp16(ms_a + tid * 16u, g_M + bh * SS + i0 + tid * 4);
    CP_COMMIT();
    cp_wait<0>();
    __syncthreads();

    const int c_start = s_cstart;
    const float M0 = sm[MS_OFF + i0w + g8];
    const float M1 = sm[MS_OFF + i0w + g8 + 8];

    // hoist Q A-fragments into registers (invariant across chunks)
    uint32_t qf0[8], qf1[8], qf2[8], qf3[8];
    #pragma unroll
    for (int ks = 0; ks < 8; ks++) {
        const float* qb = sm + QS_OFF + (i0w + g8) * 68 + ks * 8 + tg;
        qf0[ks] = __float_as_uint(qb[0]);
        qf1[ks] = __float_as_uint(qb[8 * 68]);
        qf2[ks] = __float_as_uint(qb[4]);
        qf3[ks] = __float_as_uint(qb[8 * 68 + 4]);
    }

#define STAGE_CH(cc, bufidx) do {                                             \
    int j0_ = (cc) * 64;                                                      \
    _Pragma("unroll")                                                         \
    for (int t_ = 0; t_ < 4; t_++) {                                          \
        int s_ = tid + 256 * t_, row_ = s_ >> 4, c16_ = s_ & 15;              \
        cp16(ks_a + (uint32_t)((bufidx) * 17408 + row_ * 272 + c16_ * 16),    \
             kg0 + (size_t)(j0_ + row_) * EE + c16_ * 4);                     \
        cp16(vs_a + (uint32_t)((bufidx) * 18432 + row_ * 288 + c16_ * 16),    \
             vg0 + (size_t)(j0_ + row_) * EE + c16_ * 4);                     \
    }                                                                         \
    if (tid < 16)                                                             \
        cp16(wb_a + (bufidx) * 256u + tid * 16u, g_w + bh * SS + j0_ + tid * 4); \
    else if (tid < 32)                                                        \
        cp16(ub_a + (bufidx) * 256u + (tid - 16) * 16u,                       \
             g_u + bh * SS + j0_ + (tid - 16) * 4);                           \
} while (0)

    STAGE_CH(c_start, 0);
    CP_COMMIT();
    cp_wait<0>();
    __syncthreads();                     // chunk c_start visible

    float o[4][4];
    #pragma unroll
    for (int t = 0; t < 4; t++)
        #pragma unroll
        for (int r = 0; r < 4; r++) o[t][r] = 0.f;
    float pr0 = 0.f, pr1 = 0.f;          // running row-sum partials

    for (int c = c_start; c <= ti; c++) {
        const int p = (c - c_start) & 1;

        // prefetch chunk c+1 into buffer p^1 (fenced by SYNC_B of iter c-1)
        if (c < ti) {
            STAGE_CH(c + 1, p ^ 1);
            CP_COMMIT();
        }

        const float* Ksp = sm + KS_OFF + p * 4352;
        const float* Vsp = sm + VS_OFF + p * 4608;

        // ---- GEMM1: S = Q.K^T (tf32 mma, Q frags in registers) ----
        float s4[4][4];
        #pragma unroll
        for (int t = 0; t < 4; t++)
            #pragma unroll
            for (int r = 0; r < 4; r++) s4[t][r] = 0.f;
        #pragma unroll
        for (int ks = 0; ks < 8; ks++) {
            const int k0 = ks * 8;
            #pragma unroll
            for (int t = 0; t < 4; t++) {
                const int j0 = wj * 32 + t * 8;
                const float* kbp = Ksp + (j0 + g8) * 68 + k0 + tg;
                uint32_t b0 = __float_as_uint(kbp[0]);
                uint32_t b1 = __float_as_uint(kbp[4]);
                mma_tf32(s4[t][0], s4[t][1], s4[t][2], s4[t][3],
                         qf0[ks], qf1[ks], qf2[ks], qf3[ks], b0, b1);
            }
        }

        // ---- P = scale(S) -> Ps; accumulate row partials in registers ----
        if (c < ti) {
            const float csc = sm[CS_OFF + c];
            const float e0 = 0.125f * __expf(csc - M0);
            const float e1 = 0.125f * __expf(csc - M1);
            #pragma unroll
            for (int t = 0; t < 4; t++) {
                const int jc = wj * 32 + t * 8 + tg * 2;
                float2 wv = *(const float2*)(sm + WB_OFF + p * 64 + jc);
                float2 hi = make_float2(s4[t][0] * e0 * wv.x, s4[t][1] * e0 * wv.y);
                float2 lo = make_float2(s4[t][2] * e1 * wv.x, s4[t][3] * e1 * wv.y);
                pr0 += hi.x + hi.y;
                pr1 += lo.x + lo.y;
                *(float2*)(sm + PS_OFF + (i0w + g8) * 68 + jc)     = hi;
                *(float2*)(sm + PS_OFF + (i0w + g8 + 8) * 68 + jc) = lo;
            }
        } else {
            const int il0 = i0w + g8, il1 = il0 + 8;
            #pragma unroll
            for (int t = 0; t < 4; t++) {
                const int jc = wj * 32 + t * 8 + tg * 2;
                float2 uv = *(const float2*)(sm + UB_OFF + p * 64 + jc);
                float p0 = (jc     <= il0) ? s4[t][0] * 0.125f * __expf(uv.x - M0) : 0.f;
                float p1 = (jc + 1 <= il0) ? s4[t][1] * 0.125f * __expf(uv.y - M0) : 0.f;
                float p2 = (jc     <= il1) ? s4[t][2] * 0.125f * __expf(uv.x - M1) : 0.f;
                float p3 = (jc + 1 <= il1) ? s4[t][3] * 0.125f * __expf(uv.y - M1) : 0.f;
                pr0 += p0 + p1;
                pr1 += p2 + p3;
                *(float2*)(sm + PS_OFF + (i0w + g8) * 68 + jc)     = make_float2(p0, p1);
                *(float2*)(sm + PS_OFF + (i0w + g8 + 8) * 68 + jc) = make_float2(p2, p3);
            }
        }
        __syncthreads();                 // SYNC_A: Ps visible

        // ---- GEMM2: O += P.V (tf32 mma) ----
        #pragma unroll
        for (int ks = 0; ks < 8; ks++) {
            const int k0j = ks * 8;
            const float* pb = sm + PS_OFF + (i0w + g8) * 68 + k0j + tg;
            uint32_t a0 = __float_as_uint(pb[0]);
            uint32_t a1 = __float_as_uint(pb[8 * 68]);
            uint32_t a2 = __float_as_uint(pb[4]);
            uint32_t a3 = __float_as_uint(pb[8 * 68 + 4]);
            #pragma unroll
            for (int t = 0; t < 4; t++) {
                const int d0c = wj * 32 + t * 8;
                const float* vbp = Vsp + (k0j + tg) * 72 + d0c + g8;
                uint32_t b0 = __float_as_uint(vbp[0]);
                uint32_t b1 = __float_as_uint(vbp[4 * 72]);
                mma_tf32(o[t][0], o[t][1], o[t][2], o[t][3],
                         a0, a1, a2, a3, b0, b1);
            }
        }

        if (c < ti) cp_wait<0>();        // chunk c+1 landed
        __syncthreads();                 // SYNC_B: next iter may reuse buffers
    }
#undef STAGE_CH

    // ---- epilogue ----
    // reduce ssum partials over tg (lanes sharing g8) and publish per-warp
    pr0 += __shfl_xor_sync(0xffffffffu, pr0, 1);
    pr0 += __shfl_xor_sync(0xffffffffu, pr0, 2);
    pr1 += __shfl_xor_sync(0xffffffffu, pr1, 1);
    pr1 += __shfl_xor_sync(0xffffffffu, pr1, 2);
    if (tg == 0) {
        sm[SSUM_OFF + wj * 64 + i0w + g8]     = pr0;
        sm[SSUM_OFF + wj * 64 + i0w + g8 + 8] = pr1;
    }

    // stage O to Ps (last SYNC_B fenced GEMM2 reads of Ps)
    #pragma unroll
    for (int t = 0; t < 4; t++) {
        const int dc = wj * 32 + t * 8 + tg * 2;
        *(float2*)(sm + PS_OFF + (i0w + g8) * 68 + dc)     = make_float2(o[t][0], o[t][1]);
        *(float2*)(sm + PS_OFF + (i0w + g8 + 8) * 68 + dc) = make_float2(o[t][2], o[t][3]);
    }
    __syncthreads();

    {
        const int row = tid >> 2, qq = tid & 3;
        const float ss = sm[SSUM_OFF + row] + sm[SSUM_OFF + 64 + row];

        const int gi = bh * SS + i0 + row;
        const float mi   = g_m[gi];
        const float norm = fmaxf(fabsf(ss), __expf(-mi)) + 1e-6f;
        const float inv  = 1.0f / norm;

        const float4* orp = (const float4*)(sm + PS_OFF + row * 68 + qq * 16);
        float4 y0 = orp[0], y1 = orp[1], y2 = orp[2], y3 = orp[3];

        float sum = (((y0.x + y0.y) + (y0.z + y0.w))
                   + ((y1.x + y1.y) + (y1.z + y1.w)))
                  + (((y2.x + y2.y) + (y2.z + y2.w))
                   + ((y3.x + y3.y) + (y3.z + y3.w)));
        sum += __shfl_xor_sync(0xffffffffu, sum, 1);
        sum += __shfl_xor_sync(0xffffffffu, sum, 2);
        const float mu = sum * inv * (1.0f / 64.0f);

        float vals[16] = {y0.x, y0.y, y0.z, y0.w, y1.x, y1.y, y1.z, y1.w,
                          y2.x, y2.y, y2.z, y2.w, y3.x, y3.y, y3.z, y3.w};
        float var = 0.f;
        #pragma unroll
        for (int e = 0; e < 16; e++) {
            float dx = vals[e] * inv - mu;
            var += dx * dx;
        }
        var += __shfl_xor_sync(0xffffffffu, var, 1);
        var += __shfl_xor_sync(0xffffffffu, var, 2);
        const float sc = rsqrtf(var * (1.0f / 64.0f) + 1e-5f);

        float* op = out + (size_t)gi * 64 + qq * 16;
        #pragma unroll
        for (int e4 = 0; e4 < 4; e4++) {
            *(float4*)(op + e4 * 4) = make_float4(
                (vals[e4 * 4 + 0] * inv - mu) * sc,
                (vals[e4 * 4 + 1] * inv - mu) * sc,
                (vals[e4 * 4 + 2] * inv - mu) * sc,
                (vals[e4 * 4 + 3] * inv - mu) * sc);
        }
    }
}

// ---------------------------------------------------------------------------
extern "C" void kernel_launch(void* const* d_in, const int* in_sizes, int n_in,
                              void* d_out, int out_size) {
    const float* q  = (const float*)d_in[0];
    const float* k  = (const float*)d_in[1];
    const float* v  = (const float*)d_in[2];
    const float* Wi = (const float*)d_in[3];
    const float* bi = (const float*)d_in[4];
    const float* Wf = (const float*)d_in[5];
    const float* bf = (const float*)d_in[6];
    float* out = (float*)d_out;

    cudaFuncSetAttribute(attn_kernel,
                         cudaFuncAttributeMaxDynamicSharedMemorySize,
                         ATTN_SMEM_BYTES);

    gates_kernel<<<(BB * SS) / 8, 512>>>(q, k, v, Wi, bi, Wf, bf);
    scan_kernel<<<BH, 256>>>();
    attn_kernel<<<dim3(SS / 64, BH), 256, ATTN_SMEM_BYTES>>>(q, k, v, out);
}